// round 6
// baseline (speedup 1.0000x reference)
#include <cuda_runtime.h>
#include <cstddef>

#define BATCH 16
#define LSEQ  2048
#define DIM   128
#define BM    128
#define BN    128
#define NTHREADS 256
#define TXN 16          // thread grid 16x16
#define LDS_T 129       // padded stride for transposed (d-major / j-major) tiles
#define LDS_V 132       // padded stride for V tile (multiple of 4 for float4 STS)
#define LDS_R 129       // padded stride for rowsum reduction buffer

#define SCALE 0.08838834764831845f   // 1/sqrt(128)

// scratch for per-row inverse softmax sums (written by pass1, read by pass2)
__device__ float g_inv_rowsum[BATCH * LSEQ];

// dynamic smem layout:
//   Qt  [DIM][LDS_T]  : Q tile transposed, Qt[d*LDS_T + i] = Q[i][d]
//   KPt [DIM][LDS_T]  : K tile transposed (d-major), reused as P tile (j-major)
//   Vs  [BN][LDS_V]   : V tile natural layout
//   red [TXN][LDS_R]  : rowsum reduction buffer (reused to hold inv per row)
#define SMEM_FLOATS (DIM*LDS_T + DIM*LDS_T + BN*LDS_V + TXN*LDS_R)

__global__ __launch_bounds__(NTHREADS, 1)
void attn_pass1(const float* __restrict__ q, const float* __restrict__ k,
                const float* __restrict__ v, float* __restrict__ ctx,
                float* __restrict__ attn)
{
    extern __shared__ float sm[];
    float* Qt  = sm;
    float* KPt = Qt  + DIM * LDS_T;
    float* Vs  = KPt + DIM * LDS_T;
    float* red = Vs  + BN  * LDS_V;

    const int b     = blockIdx.y;
    const int qbase = blockIdx.x * BM;
    const int tid   = threadIdx.x;
    const int tx    = tid % TXN;
    const int ty    = tid / TXN;

    const float* Qg = q + ((size_t)b * LSEQ + qbase) * DIM;
    const float* Kg = k + (size_t)b * LSEQ * DIM;
    const float* Vg = v + (size_t)b * LSEQ * DIM;

    // ---- load Q tile transposed (float4 gmem reads, scalar transposed STS) ----
    {
        const float4* Qg4 = reinterpret_cast<const float4*>(Qg);
        #pragma unroll
        for (int e = 0; e < (BM * DIM / 4) / NTHREADS; ++e) {
            int flat4 = tid + NTHREADS * e;           // over BM*DIM/4
            int i  = flat4 >> 5;                       // /32 (DIM/4)
            int d4 = flat4 & 31;
            float4 val = Qg4[flat4];
            int d = d4 * 4;
            Qt[(d + 0) * LDS_T + i] = val.x;
            Qt[(d + 1) * LDS_T + i] = val.y;
            Qt[(d + 2) * LDS_T + i] = val.z;
            Qt[(d + 3) * LDS_T + i] = val.w;
        }
    }

    float O[8][8];
    #pragma unroll
    for (int r = 0; r < 8; ++r)
        #pragma unroll
        for (int c = 0; c < 8; ++c) O[r][c] = 0.f;

    float rs[8];
    #pragma unroll
    for (int r = 0; r < 8; ++r) rs[r] = 0.f;

    for (int jt = 0; jt < LSEQ / BN; ++jt) {
        __syncthreads();   // previous P tile fully consumed before overwriting KPt

        // ---- load K tile (transposed) and V tile (natural) ----
        {
            const float4* Kg4 = reinterpret_cast<const float4*>(Kg + (size_t)jt * BN * DIM);
            const float4* Vg4 = reinterpret_cast<const float4*>(Vg + (size_t)jt * BN * DIM);
            #pragma unroll
            for (int e = 0; e < (BN * DIM / 4) / NTHREADS; ++e) {
                int flat4 = tid + NTHREADS * e;
                int j  = flat4 >> 5;
                int d4 = flat4 & 31;
                int d  = d4 * 4;
                float4 kv = Kg4[flat4];
                KPt[(d + 0) * LDS_T + j] = kv.x;
                KPt[(d + 1) * LDS_T + j] = kv.y;
                KPt[(d + 2) * LDS_T + j] = kv.z;
                KPt[(d + 3) * LDS_T + j] = kv.w;
                float4 vv = Vg4[flat4];
                *reinterpret_cast<float4*>(&Vs[j * LDS_V + d]) = vv;
            }
        }
        __syncthreads();

        // ---- S = Q K^T (8x8 register tile per thread) ----
        float S[8][8];
        #pragma unroll
        for (int r = 0; r < 8; ++r)
            #pragma unroll
            for (int c = 0; c < 8; ++c) S[r][c] = 0.f;

        #pragma unroll 4
        for (int d = 0; d < DIM; ++d) {
            float a[8], bb[8];
            #pragma unroll
            for (int r = 0; r < 8; ++r) a[r]  = Qt[d * LDS_T + ty + 16 * r];
            #pragma unroll
            for (int c = 0; c < 8; ++c) bb[c] = KPt[d * LDS_T + tx + 16 * c];
            #pragma unroll
            for (int r = 0; r < 8; ++r)
                #pragma unroll
                for (int c = 0; c < 8; ++c)
                    S[r][c] += a[r] * bb[c];
        }
        __syncthreads();   // all threads done reading K before P overwrites KPt

        // ---- P = exp(S*scale); partial rowsum; store P (j-major) into KPt ----
        #pragma unroll
        for (int r = 0; r < 8; ++r) {
            #pragma unroll
            for (int c = 0; c < 8; ++c) {
                float p = __expf(S[r][c] * SCALE);
                rs[r] += p;
                KPt[(tx + 16 * c) * LDS_T + (ty + 16 * r)] = p;
            }
        }
        __syncthreads();

        // ---- write unnormalized attention tile to gmem (coalesced float4) ----
        {
            float* Ag = attn + ((size_t)b * LSEQ + qbase) * LSEQ + (size_t)jt * BN;
            #pragma unroll
            for (int e = 0; e < (BM * BN / 4) / NTHREADS; ++e) {
                int flat4 = tid + NTHREADS * e;       // over BM*BN/4
                int i  = flat4 >> 5;
                int j4 = flat4 & 31;
                int j  = j4 * 4;
                float4 pv;
                pv.x = KPt[(j + 0) * LDS_T + i];
                pv.y = KPt[(j + 1) * LDS_T + i];
                pv.z = KPt[(j + 2) * LDS_T + i];
                pv.w = KPt[(j + 3) * LDS_T + i];
                *reinterpret_cast<float4*>(&Ag[(size_t)i * LSEQ + j]) = pv;
            }
        }

        // ---- O += P @ V ----
        #pragma unroll 4
        for (int j = 0; j < BN; ++j) {
            float a[8], bb[8];
            #pragma unroll
            for (int r = 0; r < 8; ++r) a[r]  = KPt[j * LDS_T + ty + 16 * r];
            #pragma unroll
            for (int c = 0; c < 8; ++c) bb[c] = Vs[j * LDS_V + tx + 16 * c];
            #pragma unroll
            for (int r = 0; r < 8; ++r)
                #pragma unroll
                for (int c = 0; c < 8; ++c)
                    O[r][c] += a[r] * bb[c];
        }
    }

    // ---- rowsum reduction across tx ----
    __syncthreads();
    #pragma unroll
    for (int r = 0; r < 8; ++r)
        red[tx * LDS_R + (ty + 16 * r)] = rs[r];
    __syncthreads();
    if (tid < BM) {
        float s = 0.f;
        #pragma unroll
        for (int t = 0; t < TXN; ++t) s += red[t * LDS_R + tid];
        float iv = 1.0f / s;
        red[tid] = iv;                                   // stash for context epilogue
        g_inv_rowsum[b * LSEQ + qbase + tid] = iv;       // for pass-2 normalization
    }
    __syncthreads();

    // ---- write normalized context ----
    {
        float* Cg = ctx + ((size_t)b * LSEQ + qbase) * DIM;
        #pragma unroll
        for (int r = 0; r < 8; ++r) {
            float iv = red[ty + 16 * r];
            #pragma unroll
            for (int c = 0; c < 8; ++c)
                Cg[(size_t)(ty + 16 * r) * DIM + (tx + 16 * c)] = O[r][c] * iv;
        }
    }
}

// pass 2: scale each attention row by its inverse softmax sum (pure streaming)
__global__ __launch_bounds__(256)
void attn_pass2(float* __restrict__ attn)
{
    size_t idx = (size_t)blockIdx.x * blockDim.x + threadIdx.x;  // float4 index
    // total float4 = BATCH*LSEQ*LSEQ/4, launched exactly
    size_t row = idx / (LSEQ / 4);
    float iv = g_inv_rowsum[row];
    float4* a4 = reinterpret_cast<float4*>(attn);
    float4 v = a4[idx];
    v.x *= iv; v.y *= iv; v.z *= iv; v.w *= iv;
    a4[idx] = v;
}

extern "C" void kernel_launch(void* const* d_in, const int* in_sizes, int n_in,
                              void* d_out, int out_size)
{
    const float* q = (const float*)d_in[0];
    const float* k = (const float*)d_in[1];
    const float* v = (const float*)d_in[2];

    float* ctx  = (float*)d_out;                                   // [B,L,D]
    float* attn = (float*)d_out + (size_t)BATCH * LSEQ * DIM;      // [B,L,L]

    static bool smem_set = false;
    // idempotent attribute set (not a stream op; safe under graph capture)
    cudaFuncSetAttribute(attn_pass1, cudaFuncAttributeMaxDynamicSharedMemorySize,
                         SMEM_FLOATS * (int)sizeof(float));
    (void)smem_set; (void)in_sizes; (void)n_in; (void)out_size;

    dim3 grid1(LSEQ / BM, BATCH);
    attn_pass1<<<grid1, NTHREADS, SMEM_FLOATS * sizeof(float)>>>(q, k, v, ctx, attn);

    size_t total4 = (size_t)BATCH * LSEQ * LSEQ / 4;
    attn_pass2<<<(unsigned)(total4 / 256), 256>>>(attn);
}

// round 7
// speedup vs baseline: 1.0016x; 1.0016x over previous
#include <cuda_runtime.h>
#include <cstddef>

#define BATCH 16
#define LSEQ  2048
#define DIM   128
#define BM    128
#define BN    128
#define NTHREADS 256
#define TXN 16          // thread grid 16x16
#define LDS_T 129       // padded stride for transposed (d-major / j-major) tiles
#define LDS_V 132       // padded stride for V tile (multiple of 4 for float4 STS)
#define LDS_R 129       // padded stride for rowsum reduction buffer

#define SCALE 0.08838834764831845f   // 1/sqrt(128)

// scratch for per-row inverse softmax sums (written by pass1, read by pass2)
__device__ float g_inv_rowsum[BATCH * LSEQ];

// dynamic smem layout:
//   Qt  [DIM][LDS_T]  : Q tile transposed, Qt[d*LDS_T + i] = Q[i][d]
//   KPt [DIM][LDS_T]  : K tile transposed (d-major), reused as P tile (j-major)
//   Vs  [BN][LDS_V]   : V tile natural layout
//   red [TXN][LDS_R]  : rowsum reduction buffer (reused to hold inv per row)
#define SMEM_FLOATS (DIM*LDS_T + DIM*LDS_T + BN*LDS_V + TXN*LDS_R)

__global__ __launch_bounds__(NTHREADS, 1)
void attn_pass1(const float* __restrict__ q, const float* __restrict__ k,
                const float* __restrict__ v, float* __restrict__ ctx,
                float* __restrict__ attn)
{
    extern __shared__ float sm[];
    float* Qt  = sm;
    float* KPt = Qt  + DIM * LDS_T;
    float* Vs  = KPt + DIM * LDS_T;
    float* red = Vs  + BN  * LDS_V;

    const int b     = blockIdx.y;
    const int qbase = blockIdx.x * BM;
    const int tid   = threadIdx.x;
    const int tx    = tid % TXN;
    const int ty    = tid / TXN;

    const float* Qg = q + ((size_t)b * LSEQ + qbase) * DIM;
    const float* Kg = k + (size_t)b * LSEQ * DIM;
    const float* Vg = v + (size_t)b * LSEQ * DIM;

    // ---- load Q tile transposed (float4 gmem reads, scalar transposed STS) ----
    {
        const float4* Qg4 = reinterpret_cast<const float4*>(Qg);
        #pragma unroll
        for (int e = 0; e < (BM * DIM / 4) / NTHREADS; ++e) {
            int flat4 = tid + NTHREADS * e;           // over BM*DIM/4
            int i  = flat4 >> 5;                       // /32 (DIM/4)
            int d4 = flat4 & 31;
            float4 val = Qg4[flat4];
            int d = d4 * 4;
            Qt[(d + 0) * LDS_T + i] = val.x;
            Qt[(d + 1) * LDS_T + i] = val.y;
            Qt[(d + 2) * LDS_T + i] = val.z;
            Qt[(d + 3) * LDS_T + i] = val.w;
        }
    }

    float O[8][8];
    #pragma unroll
    for (int r = 0; r < 8; ++r)
        #pragma unroll
        for (int c = 0; c < 8; ++c) O[r][c] = 0.f;

    float rs[8];
    #pragma unroll
    for (int r = 0; r < 8; ++r) rs[r] = 0.f;

    for (int jt = 0; jt < LSEQ / BN; ++jt) {
        __syncthreads();   // previous P tile fully consumed before overwriting KPt

        // ---- load K tile (transposed) and V tile (natural) ----
        {
            const float4* Kg4 = reinterpret_cast<const float4*>(Kg + (size_t)jt * BN * DIM);
            const float4* Vg4 = reinterpret_cast<const float4*>(Vg + (size_t)jt * BN * DIM);
            #pragma unroll
            for (int e = 0; e < (BN * DIM / 4) / NTHREADS; ++e) {
                int flat4 = tid + NTHREADS * e;
                int j  = flat4 >> 5;
                int d4 = flat4 & 31;
                int d  = d4 * 4;
                float4 kv = Kg4[flat4];
                KPt[(d + 0) * LDS_T + j] = kv.x;
                KPt[(d + 1) * LDS_T + j] = kv.y;
                KPt[(d + 2) * LDS_T + j] = kv.z;
                KPt[(d + 3) * LDS_T + j] = kv.w;
                float4 vv = Vg4[flat4];
                *reinterpret_cast<float4*>(&Vs[j * LDS_V + d]) = vv;
            }
        }
        __syncthreads();

        // ---- S = Q K^T (8x8 register tile per thread) ----
        float S[8][8];
        #pragma unroll
        for (int r = 0; r < 8; ++r)
            #pragma unroll
            for (int c = 0; c < 8; ++c) S[r][c] = 0.f;

        #pragma unroll 4
        for (int d = 0; d < DIM; ++d) {
            float a[8], bb[8];
            #pragma unroll
            for (int r = 0; r < 8; ++r) a[r]  = Qt[d * LDS_T + ty + 16 * r];
            #pragma unroll
            for (int c = 0; c < 8; ++c) bb[c] = KPt[d * LDS_T + tx + 16 * c];
            #pragma unroll
            for (int r = 0; r < 8; ++r)
                #pragma unroll
                for (int c = 0; c < 8; ++c)
                    S[r][c] += a[r] * bb[c];
        }
        __syncthreads();   // all threads done reading K before P overwrites KPt

        // ---- P = exp(S*scale); partial rowsum; store P (j-major) into KPt ----
        #pragma unroll
        for (int r = 0; r < 8; ++r) {
            #pragma unroll
            for (int c = 0; c < 8; ++c) {
                float p = __expf(S[r][c] * SCALE);
                rs[r] += p;
                KPt[(tx + 16 * c) * LDS_T + (ty + 16 * r)] = p;
            }
        }
        __syncthreads();

        // ---- write unnormalized attention tile to gmem (coalesced float4) ----
        {
            float* Ag = attn + ((size_t)b * LSEQ + qbase) * LSEQ + (size_t)jt * BN;
            #pragma unroll
            for (int e = 0; e < (BM * BN / 4) / NTHREADS; ++e) {
                int flat4 = tid + NTHREADS * e;       // over BM*BN/4
                int i  = flat4 >> 5;
                int j4 = flat4 & 31;
                int j  = j4 * 4;
                float4 pv;
                pv.x = KPt[(j + 0) * LDS_T + i];
                pv.y = KPt[(j + 1) * LDS_T + i];
                pv.z = KPt[(j + 2) * LDS_T + i];
                pv.w = KPt[(j + 3) * LDS_T + i];
                *reinterpret_cast<float4*>(&Ag[(size_t)i * LSEQ + j]) = pv;
            }
        }

        // ---- O += P @ V ----
        #pragma unroll 4
        for (int j = 0; j < BN; ++j) {
            float a[8], bb[8];
            #pragma unroll
            for (int r = 0; r < 8; ++r) a[r]  = KPt[j * LDS_T + ty + 16 * r];
            #pragma unroll
            for (int c = 0; c < 8; ++c) bb[c] = Vs[j * LDS_V + tx + 16 * c];
            #pragma unroll
            for (int r = 0; r < 8; ++r)
                #pragma unroll
                for (int c = 0; c < 8; ++c)
                    O[r][c] += a[r] * bb[c];
        }
    }

    // ---- rowsum reduction across tx ----
    __syncthreads();
    #pragma unroll
    for (int r = 0; r < 8; ++r)
        red[tx * LDS_R + (ty + 16 * r)] = rs[r];
    __syncthreads();
    if (tid < BM) {
        float s = 0.f;
        #pragma unroll
        for (int t = 0; t < TXN; ++t) s += red[t * LDS_R + tid];
        float iv = 1.0f / s;
        red[tid] = iv;                                   // stash for context epilogue
        g_inv_rowsum[b * LSEQ + qbase + tid] = iv;       // for pass-2 normalization
    }
    __syncthreads();

    // ---- write normalized context ----
    {
        float* Cg = ctx + ((size_t)b * LSEQ + qbase) * DIM;
        #pragma unroll
        for (int r = 0; r < 8; ++r) {
            float iv = red[ty + 16 * r];
            #pragma unroll
            for (int c = 0; c < 8; ++c)
                Cg[(size_t)(ty + 16 * r) * DIM + (tx + 16 * c)] = O[r][c] * iv;
        }
    }
}

// pass 2: scale each attention row by its inverse softmax sum (pure streaming)
__global__ __launch_bounds__(256)
void attn_pass2(float* __restrict__ attn)
{
    size_t idx = (size_t)blockIdx.x * blockDim.x + threadIdx.x;  // float4 index
    // total float4 = BATCH*LSEQ*LSEQ/4, launched exactly
    size_t row = idx / (LSEQ / 4);
    float iv = g_inv_rowsum[row];
    float4* a4 = reinterpret_cast<float4*>(attn);
    float4 v = a4[idx];
    v.x *= iv; v.y *= iv; v.z *= iv; v.w *= iv;
    a4[idx] = v;
}

extern "C" void kernel_launch(void* const* d_in, const int* in_sizes, int n_in,
                              void* d_out, int out_size)
{
    const float* q = (const float*)d_in[0];
    const float* k = (const float*)d_in[1];
    const float* v = (const float*)d_in[2];

    float* ctx  = (float*)d_out;                                   // [B,L,D]
    float* attn = (float*)d_out + (size_t)BATCH * LSEQ * DIM;      // [B,L,L]

    static bool smem_set = false;
    // idempotent attribute set (not a stream op; safe under graph capture)
    cudaFuncSetAttribute(attn_pass1, cudaFuncAttributeMaxDynamicSharedMemorySize,
                         SMEM_FLOATS * (int)sizeof(float));
    (void)smem_set; (void)in_sizes; (void)n_in; (void)out_size;

    dim3 grid1(LSEQ / BM, BATCH);
    attn_pass1<<<grid1, NTHREADS, SMEM_FLOATS * sizeof(float)>>>(q, k, v, ctx, attn);

    size_t total4 = (size_t)BATCH * LSEQ * LSEQ / 4;
    attn_pass2<<<(unsigned)(total4 / 256), 256>>>(attn);
}